// round 1
// baseline (speedup 1.0000x reference)
#include <cuda_runtime.h>
#include <cuda_fp16.h>
#include <cstdint>

// Problem dims
#define MDIM 2048      // B*S
#define NDIM 8192      // OUT*32
#define KDIM 8192      // IN*32

// Scratch (allocation-free rule: __device__ globals)
__device__ __half g_Xh[(size_t)MDIM * KDIM];           // 32 MiB
__device__ __half g_Wh[(size_t)KDIM * NDIM];           // 128 MiB

// ---------------- Cl(4,1) sign ----------------
// gp[a,b,a^b] = sign: reorder swaps parity + metric (-1 for e5 = bit 4)
__device__ __forceinline__ float gp_sign(int a, int b) {
    int swaps = 0;
    int t = a >> 1;
    while (t) { swaps += __popc(t & b); t >>= 1; }
    float s = (swaps & 1) ? -1.0f : 1.0f;
    if ((a & b) & 16) s = -s;
    return s;
}

// ---------------- Phase 1: x fp32 -> fp16 ----------------
__global__ void convert_x_kernel(const float4* __restrict__ x) {
    size_t i = (size_t)blockIdx.x * blockDim.x + threadIdx.x;  // exact grid
    float4 v = x[i];
    __half2* xh = reinterpret_cast<__half2*>(g_Xh);
    xh[2 * i]     = __floats2half2_rn(v.x, v.y);
    xh[2 * i + 1] = __floats2half2_rn(v.z, v.w);
}

// ---------------- Phase 2: expand weight -> W' [K=8192][N=8192] fp16 ----------------
// W'[(i*32+l), (o*32+kb)] = weight[o,i,l^kb] * gp_sign(l^kb, l)
__global__ void expand_w_kernel(const float* __restrict__ w) {
    int idx = blockIdx.x * blockDim.x + threadIdx.x;   // [0, 8192*256)
    if (idx >= 8192 * 256) return;
    int o    = idx & 255;
    int kidx = idx >> 8;        // i*32+l
    int i    = kidx >> 5;
    int l    = kidx & 31;

    const float4* wrow = reinterpret_cast<const float4*>(w + (size_t)(o * 256 + i) * 32);
    float wreg[32];
#pragma unroll
    for (int q = 0; q < 8; q++) {
        float4 v = wrow[q];
        wreg[4 * q]     = v.x;
        wreg[4 * q + 1] = v.y;
        wreg[4 * q + 2] = v.z;
        wreg[4 * q + 3] = v.w;
    }
    __half tmp[32];
#pragma unroll
    for (int kb = 0; kb < 32; kb++) {
        int j = l ^ kb;
        tmp[kb] = __float2half_rn(wreg[j] * gp_sign(j, l));
    }
    uint4* dst = reinterpret_cast<uint4*>(g_Wh + (size_t)kidx * NDIM + o * 32);
    const uint4* src = reinterpret_cast<const uint4*>(tmp);
    dst[0] = src[0]; dst[1] = src[1]; dst[2] = src[2]; dst[3] = src[3];
}

// ---------------- Phase 3: GEMM C[M,N] = A[M,K] * B[K,N], fp16 in / fp32 acc ----------------
#define BM 128
#define BN 128
#define BK 32
#define LDA 40    // BK + 8 halves pad (80B row stride, conflict-free ldmatrix)
#define LDB 136   // BN + 8 halves pad (272B row stride)

__device__ __forceinline__ uint32_t smem_u32(const void* p) {
    return (uint32_t)__cvta_generic_to_shared(p);
}
__device__ __forceinline__ void cp_async16(uint32_t s, const void* g) {
    asm volatile("cp.async.cg.shared.global [%0], [%1], 16;\n" :: "r"(s), "l"(g));
}

__global__ void __launch_bounds__(256) gemm_kernel(float* __restrict__ C) {
    __shared__ __half sA[2][BM * LDA];
    __shared__ __half sB[2][BK * LDB];

    const int bm = blockIdx.x * BM;   // m-fast rasterization: B stripe read ~once total
    const int bn = blockIdx.y * BN;
    const int tid  = threadIdx.x;
    const int lane = tid & 31;
    const int warp = tid >> 5;
    const int wm = (warp & 3) * 32;   // 4 warps along M
    const int wn = (warp >> 2) * 64;  // 2 warps along N

    const __half* A = g_Xh;
    const __half* B = g_Wh;

    float acc[2][8][4];
#pragma unroll
    for (int a = 0; a < 2; a++)
#pragma unroll
        for (int b = 0; b < 8; b++)
#pragma unroll
            for (int c = 0; c < 4; c++) acc[a][b][c] = 0.0f;

    auto load_tile = [&](int kt, int buf) {
        const int k0 = kt * BK;
#pragma unroll
        for (int it = 0; it < 2; it++) {            // A: 128x32 halves, 512 x 16B
            int c = tid + it * 256;
            int r = c >> 2, cc = (c & 3) * 8;
            cp_async16(smem_u32(&sA[buf][r * LDA + cc]),
                       A + (size_t)(bm + r) * KDIM + k0 + cc);
        }
#pragma unroll
        for (int it = 0; it < 2; it++) {            // B: 32x128 halves, 512 x 16B
            int c = tid + it * 256;
            int r = c >> 4, cc = (c & 15) * 8;
            cp_async16(smem_u32(&sB[buf][r * LDB + cc]),
                       B + (size_t)(k0 + r) * NDIM + bn + cc);
        }
        asm volatile("cp.async.commit_group;\n");
    };

    load_tile(0, 0);
    const int NT = KDIM / BK;   // 256
    for (int t = 0; t < NT; t++) {
        const int buf = t & 1;
        if (t + 1 < NT) {
            load_tile(t + 1, buf ^ 1);
            asm volatile("cp.async.wait_group 1;\n");   // tile t landed, t+1 in flight
        } else {
            asm volatile("cp.async.wait_group 0;\n");
        }
        __syncthreads();

#pragma unroll
        for (int ks = 0; ks < 2; ks++) {
            uint32_t a[2][4];
#pragma unroll
            for (int mi = 0; mi < 2; mi++) {
                int row = wm + mi * 16 + (lane & 15);
                int col = ks * 16 + (lane >> 4) * 8;
                uint32_t addr = smem_u32(&sA[buf][row * LDA + col]);
                asm volatile("ldmatrix.sync.aligned.m8n8.x4.shared.b16 {%0,%1,%2,%3}, [%4];\n"
                             : "=r"(a[mi][0]), "=r"(a[mi][1]), "=r"(a[mi][2]), "=r"(a[mi][3])
                             : "r"(addr));
            }
            uint32_t b[8][2];
#pragma unroll
            for (int nj = 0; nj < 4; nj++) {
                int row = ks * 16 + (lane & 15);
                int col = wn + nj * 16 + (lane >> 4) * 8;
                uint32_t addr = smem_u32(&sB[buf][row * LDB + col]);
                asm volatile("ldmatrix.sync.aligned.m8n8.x4.trans.shared.b16 {%0,%1,%2,%3}, [%4];\n"
                             : "=r"(b[2 * nj][0]), "=r"(b[2 * nj][1]),
                               "=r"(b[2 * nj + 1][0]), "=r"(b[2 * nj + 1][1])
                             : "r"(addr));
            }
#pragma unroll
            for (int mi = 0; mi < 2; mi++)
#pragma unroll
                for (int nj = 0; nj < 8; nj++) {
                    asm volatile(
                        "mma.sync.aligned.m16n8k16.row.col.f32.f16.f16.f32 "
                        "{%0,%1,%2,%3},{%4,%5,%6,%7},{%8,%9},{%0,%1,%2,%3};\n"
                        : "+f"(acc[mi][nj][0]), "+f"(acc[mi][nj][1]),
                          "+f"(acc[mi][nj][2]), "+f"(acc[mi][nj][3])
                        : "r"(a[mi][0]), "r"(a[mi][1]), "r"(a[mi][2]), "r"(a[mi][3]),
                          "r"(b[nj][0]), "r"(b[nj][1]));
                }
        }
        __syncthreads();
    }

    // Epilogue: standard m16n8 accumulator mapping
#pragma unroll
    for (int mi = 0; mi < 2; mi++)
#pragma unroll
        for (int nj = 0; nj < 8; nj++) {
            int r = bm + wm + mi * 16 + (lane >> 2);
            int cc = bn + wn + nj * 8 + (lane & 3) * 2;
            *reinterpret_cast<float2*>(&C[(size_t)r * NDIM + cc]) =
                make_float2(acc[mi][nj][0], acc[mi][nj][1]);
            *reinterpret_cast<float2*>(&C[(size_t)(r + 8) * NDIM + cc]) =
                make_float2(acc[mi][nj][2], acc[mi][nj][3]);
        }
}

// ---------------- Phase 4: per-multivector normalization (32 lanes = 1 warp) ----------------
__global__ void normalize_kernel(float* __restrict__ out) {
    size_t g = (size_t)blockIdx.x * blockDim.x + threadIdx.x;   // exact grid
    float v = out[g];
    float ss = v * v;
#pragma unroll
    for (int off = 16; off; off >>= 1) ss += __shfl_xor_sync(0xffffffffu, ss, off);
    out[g] = v * rsqrtf(ss + 1e-6f);
}

// ---------------- launch ----------------
extern "C" void kernel_launch(void* const* d_in, const int* in_sizes, int n_in,
                              void* d_out, int out_size) {
    const float* x = (const float*)d_in[0];   // [2,1024,256,32] fp32
    const float* w = (const float*)d_in[1];   // [256,256,32]   fp32
    float* out = (float*)d_out;               // [2,1024,256,32] fp32

    // 1) x -> fp16   (16,777,216 floats = 4,194,304 float4)
    convert_x_kernel<<<16384, 256>>>((const float4*)x);

    // 2) weight -> expanded W' fp16 [8192 x 8192]   (8192*256 threads)
    expand_w_kernel<<<8192, 256>>>(w);

    // 3) GEMM 2048 x 8192 x 8192
    dim3 grid(MDIM / BM, NDIM / BN);   // (16, 64), m-fast
    gemm_kernel<<<grid, 256>>>(out);

    // 4) normalize each 32-lane multivector in place
    normalize_kernel<<<65536, 256>>>(out);
}